// round 1
// baseline (speedup 1.0000x reference)
#include <cuda_runtime.h>
#include <cuda_bf16.h>
#include <cstddef>

// Problem constants
#define BB 4
#define TT 2048
#define CC 1024
#define HH 16
#define DK 64
#define BT (BB*TT)        // 8192
#define C3 (3*CC)         // 3072

// Scratch (allocation-free rule: device globals)
__device__ float g_qkv[(size_t)BT * C3];   // 96 MB: (B*T, 3C) = q|k|v
__device__ float g_att[(size_t)BT * CC];   // 32 MB: attention output (B,T,C)

// ---------------------------------------------------------------------------
// GEMM: C[M,N] = A[M,K] @ B[N,K]^T   (torch Linear convention)
// 128x128 tile, KT=16, 256 threads, 8x8 per thread, fp32.
// M,N multiples of 128; K multiple of 16 (true for all our calls).
// ---------------------------------------------------------------------------
__global__ __launch_bounds__(256, 2) void gemm_nt_kernel(
    const float* __restrict__ A, const float* __restrict__ B,
    float* __restrict__ C, int M, int N, int K)
{
    __shared__ float As[16][132];   // [k][m], padded
    __shared__ float Bs[16][132];   // [k][n], padded

    const int tid  = threadIdx.x;
    const int bm   = blockIdx.y * 128;
    const int bn   = blockIdx.x * 128;
    const int row0 = (tid >> 4) * 8;     // 0..120
    const int col0 = (tid & 15) * 8;
    const int lr   = tid >> 2;           // 0..63
    const int lc   = (tid & 3) * 4;      // 0,4,8,12

    float acc[8][8];
#pragma unroll
    for (int i = 0; i < 8; i++)
#pragma unroll
        for (int j = 0; j < 8; j++) acc[i][j] = 0.0f;

    const float* Aptr = A + (size_t)(bm + lr) * K + lc;
    const float* Bptr = B + (size_t)(bn + lr) * K + lc;

    for (int kk = 0; kk < K; kk += 16) {
        float4 a0 = *(const float4*)(Aptr + kk);
        float4 a1 = *(const float4*)(Aptr + (size_t)64 * K + kk);
        float4 b0 = *(const float4*)(Bptr + kk);
        float4 b1 = *(const float4*)(Bptr + (size_t)64 * K + kk);

        __syncthreads();   // prior tile fully consumed
        As[lc+0][lr] = a0.x; As[lc+1][lr] = a0.y; As[lc+2][lr] = a0.z; As[lc+3][lr] = a0.w;
        As[lc+0][lr+64] = a1.x; As[lc+1][lr+64] = a1.y; As[lc+2][lr+64] = a1.z; As[lc+3][lr+64] = a1.w;
        Bs[lc+0][lr] = b0.x; Bs[lc+1][lr] = b0.y; Bs[lc+2][lr] = b0.z; Bs[lc+3][lr] = b0.w;
        Bs[lc+0][lr+64] = b1.x; Bs[lc+1][lr+64] = b1.y; Bs[lc+2][lr+64] = b1.z; Bs[lc+3][lr+64] = b1.w;
        __syncthreads();

#pragma unroll
        for (int k = 0; k < 16; k++) {
            float a[8], b[8];
            *(float4*)&a[0] = *(const float4*)&As[k][row0];
            *(float4*)&a[4] = *(const float4*)&As[k][row0 + 4];
            *(float4*)&b[0] = *(const float4*)&Bs[k][col0];
            *(float4*)&b[4] = *(const float4*)&Bs[k][col0 + 4];
#pragma unroll
            for (int i = 0; i < 8; i++)
#pragma unroll
                for (int j = 0; j < 8; j++)
                    acc[i][j] = fmaf(a[i], b[j], acc[i][j]);
        }
    }

#pragma unroll
    for (int i = 0; i < 8; i++) {
        float* cp = C + (size_t)(bm + row0 + i) * N + bn + col0;
#pragma unroll
        for (int j = 0; j < 8; j += 4) {
            float4 v = make_float4(acc[i][j], acc[i][j+1], acc[i][j+2], acc[i][j+3]);
            *(float4*)(cp + j) = v;
        }
    }
}

// ---------------------------------------------------------------------------
// Flash attention, causal, fp32. One CTA = one (b, h, 64-query block).
// 256 threads as 16x16: thread (ty,tx) owns S/O micro-tile rows ty*4..+3,
// cols tx*4..+3. Row reductions via shfl across the 16 tx lanes.
// ---------------------------------------------------------------------------
#define APAD 68
#define ATTN_SMEM (4 * 64 * APAD * 4)   // Qs,Ks,Vs,Ps = 69632 B

__global__ __launch_bounds__(256) void attn_kernel()
{
    extern __shared__ float sm[];
    float* Qs = sm;                 // [d][m]  transposed
    float* Ks = Qs + 64 * APAD;     // [d][n]  transposed
    float* Vs = Ks + 64 * APAD;     // [n][d]  natural
    float* Ps = Vs + 64 * APAD;     // [n][m]  transposed

    const int tid = threadIdx.x;
    const int ty  = tid >> 4;          // 0..15
    const int tx  = tid & 15;          // 0..15
    const int qb  = blockIdx.x;        // 0..31 query block
    const int b   = blockIdx.y >> 4;   // batch
    const int h   = blockIdx.y & 15;   // head

    const size_t row_base = (size_t)b * TT;
    const int    coff     = h * DK;

    // load Q block, transposed
    {
        const int r  = tid >> 4;
        const int c4 = (tid & 15) * 4;
#pragma unroll
        for (int rr = 0; rr < 4; rr++) {
            int m = r + rr * 16;
            size_t grow = row_base + (size_t)qb * 64 + m;
            float4 v = *(const float4*)&g_qkv[grow * C3 + coff + c4];
            Qs[(c4+0)*APAD + m] = v.x;
            Qs[(c4+1)*APAD + m] = v.y;
            Qs[(c4+2)*APAD + m] = v.z;
            Qs[(c4+3)*APAD + m] = v.w;
        }
    }

    float m_i[4], l_i[4], acc[4][4];
#pragma unroll
    for (int i = 0; i < 4; i++) {
        m_i[i] = -1e30f; l_i[i] = 0.0f;
#pragma unroll
        for (int j = 0; j < 4; j++) acc[i][j] = 0.0f;
    }

    for (int jb = 0; jb <= qb; jb++) {
        __syncthreads();   // previous tile (and initial Q store) consumed
        // load K (transposed) and V (natural)
        {
            const int r  = tid >> 4;
            const int c4 = (tid & 15) * 4;
#pragma unroll
            for (int rr = 0; rr < 4; rr++) {
                int n = r + rr * 16;
                size_t grow = row_base + (size_t)jb * 64 + n;
                const float* base = &g_qkv[grow * C3 + coff];
                float4 kv = *(const float4*)(base + CC + c4);
                Ks[(c4+0)*APAD + n] = kv.x;
                Ks[(c4+1)*APAD + n] = kv.y;
                Ks[(c4+2)*APAD + n] = kv.z;
                Ks[(c4+3)*APAD + n] = kv.w;
                float4 vv = *(const float4*)(base + 2*CC + c4);
                *(float4*)&Vs[n*APAD + c4] = vv;
            }
        }
        __syncthreads();

        // S = Q K^T
        float s[4][4];
#pragma unroll
        for (int i = 0; i < 4; i++)
#pragma unroll
            for (int j = 0; j < 4; j++) s[i][j] = 0.0f;
#pragma unroll 8
        for (int d = 0; d < 64; d++) {
            float q[4], k[4];
            *(float4*)q = *(const float4*)&Qs[d*APAD + ty*4];
            *(float4*)k = *(const float4*)&Ks[d*APAD + tx*4];
#pragma unroll
            for (int i = 0; i < 4; i++)
#pragma unroll
                for (int j = 0; j < 4; j++)
                    s[i][j] = fmaf(q[i], k[j], s[i][j]);
        }

        // scale + causal mask + online softmax
        const float scale = 0.125f;   // 1/sqrt(64)
#pragma unroll
        for (int i = 0; i < 4; i++) {
            const int gq = qb*64 + ty*4 + i;
            float rmax = -1e30f;
#pragma unroll
            for (int j = 0; j < 4; j++) {
                const int gk = jb*64 + tx*4 + j;
                float v = (gk <= gq) ? s[i][j] * scale : -1e30f;
                s[i][j] = v;
                rmax = fmaxf(rmax, v);
            }
#pragma unroll
            for (int mm = 8; mm >= 1; mm >>= 1)
                rmax = fmaxf(rmax, __shfl_xor_sync(0xffffffffu, rmax, mm));
            const float mnew = fmaxf(m_i[i], rmax);
            const float corr = __expf(m_i[i] - mnew);
            float rsum = 0.0f;
#pragma unroll
            for (int j = 0; j < 4; j++) {
                float p = __expf(s[i][j] - mnew);
                s[i][j] = p;
                rsum += p;
            }
#pragma unroll
            for (int mm = 8; mm >= 1; mm >>= 1)
                rsum += __shfl_xor_sync(0xffffffffu, rsum, mm);
            l_i[i] = l_i[i] * corr + rsum;
            m_i[i] = mnew;
#pragma unroll
            for (int j = 0; j < 4; j++) acc[i][j] *= corr;
        }

        // stage P transposed: Ps[n][m]
#pragma unroll
        for (int j = 0; j < 4; j++) {
            float4 pv = make_float4(s[0][j], s[1][j], s[2][j], s[3][j]);
            *(float4*)&Ps[(tx*4 + j)*APAD + ty*4] = pv;
        }
        __syncthreads();

        // O += P @ V
#pragma unroll 8
        for (int n = 0; n < 64; n++) {
            float p[4], v[4];
            *(float4*)p = *(const float4*)&Ps[n*APAD + ty*4];
            *(float4*)v = *(const float4*)&Vs[n*APAD + tx*4];
#pragma unroll
            for (int i = 0; i < 4; i++)
#pragma unroll
                for (int j = 0; j < 4; j++)
                    acc[i][j] = fmaf(p[i], v[j], acc[i][j]);
        }
    }

    // epilogue: normalize and store to g_att (B,T,C layout)
#pragma unroll
    for (int i = 0; i < 4; i++) {
        const float inv = 1.0f / l_i[i];
        size_t grow = row_base + (size_t)qb * 64 + ty*4 + i;
        float4 o = make_float4(acc[i][0]*inv, acc[i][1]*inv, acc[i][2]*inv, acc[i][3]*inv);
        *(float4*)&g_att[grow * CC + coff + tx*4] = o;
    }
}

// ---------------------------------------------------------------------------
extern "C" void kernel_launch(void* const* d_in, const int* in_sizes, int n_in,
                              void* d_out, int out_size)
{
    const float* x    = (const float*)d_in[0];   // (B,T,C)
    const float* Wqkv = (const float*)d_in[1];   // (3C, C)
    const float* Wo   = (const float*)d_in[2];   // (C, C)
    float* out        = (float*)d_out;           // (B,T,C)

    float *qkv, *att;
    cudaGetSymbolAddress((void**)&qkv, g_qkv);
    cudaGetSymbolAddress((void**)&att, g_att);

    cudaFuncSetAttribute(attn_kernel,
                         cudaFuncAttributeMaxDynamicSharedMemorySize, ATTN_SMEM);

    // 1) qkv = x @ Wqkv^T : (8192,3072,1024)
    {
        dim3 grid(C3 / 128, BT / 128);
        gemm_nt_kernel<<<grid, 256>>>(x, Wqkv, qkv, BT, C3, CC);
    }
    // 2) causal flash attention
    {
        dim3 grid(TT / 64, BB * HH);
        attn_kernel<<<grid, 256, ATTN_SMEM>>>();
    }
    // 3) out = att @ Wo^T : (8192,1024,1024)
    {
        dim3 grid(CC / 128, BT / 128);
        gemm_nt_kernel<<<grid, 256>>>(att, Wo, out, BT, CC, CC);
    }
}

// round 3
// speedup vs baseline: 1.4305x; 1.4305x over previous
#include <cuda_runtime.h>
#include <cuda_bf16.h>
#include <cstdint>
#include <cstddef>

// Problem constants
#define BB 4
#define TT 2048
#define CC 1024
#define HH 16
#define DK 64
#define BT (BB*TT)        // 8192
#define C3 (3*CC)         // 3072

// ---------------------------------------------------------------------------
// Scratch (allocation-free rule: device globals)
// ---------------------------------------------------------------------------
__device__ float g_qkv[(size_t)BT * C3];   // 96 MB fp32 (q|k|v)
__device__ float g_att[(size_t)BT * CC];   // 32 MB fp32 attention out
__device__ __nv_bfloat16 g_xh[(size_t)BT * CC],  g_xl[(size_t)BT * CC];
__device__ __nv_bfloat16 g_wqh[(size_t)C3 * CC], g_wql[(size_t)C3 * CC];
__device__ __nv_bfloat16 g_woh[(size_t)CC * CC], g_wol[(size_t)CC * CC];
__device__ __nv_bfloat16 g_ah[(size_t)BT * CC],  g_al[(size_t)BT * CC];

extern __shared__ char dynsm[];

__device__ __forceinline__ uint32_t smem_to_u32(const void* p) {
    uint32_t a;
    asm("{ .reg .u64 t; cvta.to.shared.u64 t, %1; cvt.u32.u64 %0, t; }"
        : "=r"(a) : "l"(p));
    return a;
}

__device__ __forceinline__ void mma_bf16(float* c, const uint32_t* a, const uint32_t* b) {
    asm volatile("mma.sync.aligned.m16n8k16.row.col.f32.bf16.bf16.f32 "
        "{%0,%1,%2,%3}, {%4,%5,%6,%7}, {%8,%9}, {%0,%1,%2,%3};"
        : "+f"(c[0]), "+f"(c[1]), "+f"(c[2]), "+f"(c[3])
        : "r"(a[0]), "r"(a[1]), "r"(a[2]), "r"(a[3]), "r"(b[0]), "r"(b[1]));
}
__device__ __forceinline__ void ldsm_x4(uint32_t* r, uint32_t addr) {
    asm volatile("ldmatrix.sync.aligned.m8n8.x4.shared.b16 {%0,%1,%2,%3}, [%4];"
        : "=r"(r[0]), "=r"(r[1]), "=r"(r[2]), "=r"(r[3]) : "r"(addr));
}
__device__ __forceinline__ void ldsm_x2(uint32_t* r, uint32_t addr) {
    asm volatile("ldmatrix.sync.aligned.m8n8.x2.shared.b16 {%0,%1}, [%2];"
        : "=r"(r[0]), "=r"(r[1]) : "r"(addr));
}
#define CP_ASYNC16(dst, src) \
    asm volatile("cp.async.cg.shared.global [%0], [%1], 16;" :: "r"(dst), "l"(src))
#define CP_COMMIT()  asm volatile("cp.async.commit_group;" ::: "memory")
#define CP_WAIT1()   asm volatile("cp.async.wait_group 1;" ::: "memory")

// ---------------------------------------------------------------------------
// Split-bf16 conversion: hi = bf16(x); lo = bf16(x - hi)
// ---------------------------------------------------------------------------
__global__ void cvt_split_kernel(const float4* __restrict__ src,
                                 __nv_bfloat162* __restrict__ hi,
                                 __nv_bfloat162* __restrict__ lo, int n4)
{
    int i = blockIdx.x * blockDim.x + threadIdx.x;
    if (i >= n4) return;
    float4 v = src[i];
    float f[4] = {v.x, v.y, v.z, v.w};
    __nv_bfloat16 h[4], l[4];
#pragma unroll
    for (int j = 0; j < 4; j++) {
        h[j] = __float2bfloat16(f[j]);
        l[j] = __float2bfloat16(f[j] - __bfloat162float(h[j]));
    }
    __nv_bfloat162 h0; h0.x = h[0]; h0.y = h[1];
    __nv_bfloat162 h1; h1.x = h[2]; h1.y = h[3];
    __nv_bfloat162 l0; l0.x = l[0]; l0.y = l[1];
    __nv_bfloat162 l1; l1.x = l[2]; l1.y = l[3];
    hi[2*i] = h0; hi[2*i+1] = h1;
    lo[2*i] = l0; lo[2*i+1] = l1;
}

// ---------------------------------------------------------------------------
// HMMA split-bf16 GEMM: C[M,N] = (Ah+Al)[M,K] @ (Bh+Bl)[N,K]^T  (3 products)
// 128x128 tile, BK=32, 8 warps (64x32 each), cp.async 3-stage pipeline.
// Smem rows: 32 bf16 data padded to 40 (80B stride -> ldmatrix conflict-free).
// ---------------------------------------------------------------------------
#define RS_B    80                  // row stride bytes
#define TILE_B  (128*RS_B)          // 10240
#define STAGE_B (4*TILE_B)          // Ah,Al,Bh,Bl = 40960
#define STAGES  3
#define GEMM_SMEM (STAGES*STAGE_B)  // 122880

__global__ __launch_bounds__(256, 1) void gemm_bf16x3_kernel(
    const __nv_bfloat16* __restrict__ Ah, const __nv_bfloat16* __restrict__ Al,
    const __nv_bfloat16* __restrict__ Bh, const __nv_bfloat16* __restrict__ Bl,
    float* __restrict__ C, int M, int N, int K)
{
    const int tid = threadIdx.x, lane = tid & 31, wid = tid >> 5;
    const int bm = blockIdx.y * 128, bn = blockIdx.x * 128;
    const int wr = wid >> 2, wc = wid & 3;      // warp tile: rows wr*64, cols wc*32
    const uint32_t sbase = smem_to_u32(dynsm);
    const int NC = K / 32;

    float acc[4][4][4];
#pragma unroll
    for (int i = 0; i < 4; i++)
#pragma unroll
        for (int j = 0; j < 4; j++)
#pragma unroll
            for (int v = 0; v < 4; v++) acc[i][j][v] = 0.0f;

    // per-thread cp.async source row/chunk (8 chunks of 16B per thread)
    auto load_stage = [&](int st, int buf) {
        const int kk = st * 32;
        const uint32_t dstb = sbase + buf * STAGE_B;
#pragma unroll
        for (int i = 0; i < 8; i++) {
            int c = tid + i * 256;                 // 0..2047
            int tile = c >> 9;                     // 0..3
            int rc = c & 511;
            int row = rc >> 2, kc = rc & 3;
            const __nv_bfloat16* src;
            if (tile == 0)      src = Ah + (size_t)(bm + row) * K + kk + kc * 8;
            else if (tile == 1) src = Al + (size_t)(bm + row) * K + kk + kc * 8;
            else if (tile == 2) src = Bh + (size_t)(bn + row) * K + kk + kc * 8;
            else                src = Bl + (size_t)(bn + row) * K + kk + kc * 8;
            uint32_t dst = dstb + tile * TILE_B + row * RS_B + kc * 16;
            CP_ASYNC16(dst, src);
        }
    };

    // lane-derived ldmatrix offsets
    const uint32_t a_off0 = (wr * 64 + (lane & 15)) * RS_B + (lane >> 4) * 16;
    const uint32_t b_off0 = (wc * 32 + (lane & 7)) * RS_B + ((lane >> 3) & 1) * 16;

    // prologue: stages 0,1
    load_stage(0, 0); CP_COMMIT();
    load_stage(1, 1); CP_COMMIT();

    for (int it = 0; it < NC; it++) {
        CP_WAIT1();
        __syncthreads();
        const int nxt = it + (STAGES - 1);
        if (nxt < NC) load_stage(nxt, nxt % STAGES);
        CP_COMMIT();

        const uint32_t tb = sbase + (it % STAGES) * STAGE_B;
#pragma unroll
        for (int ks = 0; ks < 2; ks++) {
            uint32_t ah[4][4], al[4][4];
#pragma unroll
            for (int mt = 0; mt < 4; mt++) {
                uint32_t aaddr = tb + a_off0 + mt * (16 * RS_B) + ks * 32;
                ldsm_x4(ah[mt], aaddr);
                ldsm_x4(al[mt], aaddr + TILE_B);
            }
#pragma unroll
            for (int nt = 0; nt < 4; nt++) {
                uint32_t baddr = tb + 2 * TILE_B + b_off0 + nt * (8 * RS_B) + ks * 32;
                uint32_t bh[2], bl[2];
                ldsm_x2(bh, baddr);
                ldsm_x2(bl, baddr + TILE_B);
#pragma unroll
                for (int mt = 0; mt < 4; mt++) mma_bf16(acc[mt][nt], ah[mt], bh);
#pragma unroll
                for (int mt = 0; mt < 4; mt++) mma_bf16(acc[mt][nt], al[mt], bh);
#pragma unroll
                for (int mt = 0; mt < 4; mt++) mma_bf16(acc[mt][nt], ah[mt], bl);
            }
        }
    }

    // epilogue
    const int g = lane >> 2, t = lane & 3;
#pragma unroll
    for (int mt = 0; mt < 4; mt++) {
#pragma unroll
        for (int nt = 0; nt < 4; nt++) {
            int row = bm + wr * 64 + mt * 16 + g;
            int col = bn + wc * 32 + nt * 8 + t * 2;
            float2 v0 = make_float2(acc[mt][nt][0], acc[mt][nt][1]);
            float2 v1 = make_float2(acc[mt][nt][2], acc[mt][nt][3]);
            *(float2*)&C[(size_t)row * N + col]       = v0;
            *(float2*)&C[(size_t)(row + 8) * N + col] = v1;
        }
    }
}

// ---------------------------------------------------------------------------
// Flash attention, causal, fp32 SIMT (unchanged; target of next round)
// ---------------------------------------------------------------------------
#define APAD 68
#define ATTN_SMEM (4 * 64 * APAD * 4)   // 69632 B

__global__ __launch_bounds__(256) void attn_kernel()
{
    float* sm = (float*)dynsm;
    float* Qs = sm;                 // [d][m]
    float* Ks = Qs + 64 * APAD;     // [d][n]
    float* Vs = Ks + 64 * APAD;     // [n][d]
    float* Ps = Vs + 64 * APAD;     // [n][m]

    const int tid = threadIdx.x;
    const int ty  = tid >> 4;
    const int tx  = tid & 15;
    const int qb  = blockIdx.x;
    const int b   = blockIdx.y >> 4;
    const int h   = blockIdx.y & 15;

    const size_t row_base = (size_t)b * TT;
    const int    coff     = h * DK;

    {
        const int r  = tid >> 4;
        const int c4 = (tid & 15) * 4;
#pragma unroll
        for (int rr = 0; rr < 4; rr++) {
            int m = r + rr * 16;
            size_t grow = row_base + (size_t)qb * 64 + m;
            float4 v = *(const float4*)&g_qkv[grow * C3 + coff + c4];
            Qs[(c4+0)*APAD + m] = v.x;
            Qs[(c4+1)*APAD + m] = v.y;
            Qs[(c4+2)*APAD + m] = v.z;
            Qs[(c4+3)*APAD + m] = v.w;
        }
    }

    float m_i[4], l_i[4], acc[4][4];
#pragma unroll
    for (int i = 0; i < 4; i++) {
        m_i[i] = -1e30f; l_i[i] = 0.0f;
#pragma unroll
        for (int j = 0; j < 4; j++) acc[i][j] = 0.0f;
    }

    for (int jb = 0; jb <= qb; jb++) {
        __syncthreads();
        {
            const int r  = tid >> 4;
            const int c4 = (tid & 15) * 4;
#pragma unroll
            for (int rr = 0; rr < 4; rr++) {
                int n = r + rr * 16;
                size_t grow = row_base + (size_t)jb * 64 + n;
                const float* base = &g_qkv[grow * C3 + coff];
                float4 kv = *(const float4*)(base + CC + c4);
                Ks[(c4+0)*APAD + n] = kv.x;
                Ks[(c4+1)*APAD + n] = kv.y;
                Ks[(c4+2)*APAD + n] = kv.z;
                Ks[(c4+3)*APAD + n] = kv.w;
                float4 vv = *(const float4*)(base + 2*CC + c4);
                *(float4*)&Vs[n*APAD + c4] = vv;
            }
        }
        __syncthreads();

        float s[4][4];
#pragma unroll
        for (int i = 0; i < 4; i++)
#pragma unroll
            for (int j = 0; j < 4; j++) s[i][j] = 0.0f;
#pragma unroll 8
        for (int d = 0; d < 64; d++) {
            float q[4], k[4];
            *(float4*)q = *(const float4*)&Qs[d*APAD + ty*4];
            *(float4*)k = *(const float4*)&Ks[d*APAD + tx*4];
#pragma unroll
            for (int i = 0; i < 4; i++)
#pragma unroll
                for (int j = 0; j < 4; j++)
                    s[i][j] = fmaf(q[i], k[j], s[i][j]);
        }

        const float scale = 0.125f;
#pragma unroll
        for (int i = 0; i < 4; i++) {
            const int gq = qb*64 + ty*4 + i;
            float rmax = -1e30f;
#pragma unroll
            for (int j = 0; j < 4; j++) {
                const int gk = jb*64 + tx*4 + j;
                float v = (gk <= gq) ? s[i][j] * scale : -1e30f;
                s[i][j] = v;
                rmax = fmaxf(rmax, v);
            }
#pragma unroll
            for (int mm = 8; mm >= 1; mm >>= 1)
                rmax = fmaxf(rmax, __shfl_xor_sync(0xffffffffu, rmax, mm));
            const float mnew = fmaxf(m_i[i], rmax);
            const float corr = __expf(m_i[i] - mnew);
            float rsum = 0.0f;
#pragma unroll
            for (int j = 0; j < 4; j++) {
                float p = __expf(s[i][j] - mnew);
                s[i][j] = p;
                rsum += p;
            }
#pragma unroll
            for (int mm = 8; mm >= 1; mm >>= 1)
                rsum += __shfl_xor_sync(0xffffffffu, rsum, mm);
            l_i[i] = l_i[i] * corr + rsum;
            m_i[i] = mnew;
#pragma unroll
            for (int j = 0; j < 4; j++) acc[i][j] *= corr;
        }

#pragma unroll
        for (int j = 0; j < 4; j++) {
            float4 pv = make_float4(s[0][j], s[1][j], s[2][j], s[3][j]);
            *(float4*)&Ps[(tx*4 + j)*APAD + ty*4] = pv;
        }
        __syncthreads();

#pragma unroll 8
        for (int n = 0; n < 64; n++) {
            float p[4], v[4];
            *(float4*)p = *(const float4*)&Ps[n*APAD + ty*4];
            *(float4*)v = *(const float4*)&Vs[n*APAD + tx*4];
#pragma unroll
            for (int i = 0; i < 4; i++)
#pragma unroll
                for (int j = 0; j < 4; j++)
                    acc[i][j] = fmaf(p[i], v[j], acc[i][j]);
        }
    }

#pragma unroll
    for (int i = 0; i < 4; i++) {
        const float inv = 1.0f / l_i[i];
        size_t grow = row_base + (size_t)qb * 64 + ty*4 + i;
        float4 o = make_float4(acc[i][0]*inv, acc[i][1]*inv, acc[i][2]*inv, acc[i][3]*inv);
        *(float4*)&g_att[grow * CC + coff + tx*4] = o;
    }
}

// ---------------------------------------------------------------------------
extern "C" void kernel_launch(void* const* d_in, const int* in_sizes, int n_in,
                              void* d_out, int out_size)
{
    const float* x    = (const float*)d_in[0];   // (B,T,C)
    const float* Wqkv = (const float*)d_in[1];   // (3C, C)
    const float* Wo   = (const float*)d_in[2];   // (C, C)
    float* out        = (float*)d_out;           // (B,T,C)

    float *qkv, *att;
    __nv_bfloat16 *xh, *xl, *wqh, *wql, *woh, *wol, *ah, *al;
    cudaGetSymbolAddress((void**)&qkv, g_qkv);
    cudaGetSymbolAddress((void**)&att, g_att);
    cudaGetSymbolAddress((void**)&xh, g_xh);   cudaGetSymbolAddress((void**)&xl, g_xl);
    cudaGetSymbolAddress((void**)&wqh, g_wqh); cudaGetSymbolAddress((void**)&wql, g_wql);
    cudaGetSymbolAddress((void**)&woh, g_woh); cudaGetSymbolAddress((void**)&wol, g_wol);
    cudaGetSymbolAddress((void**)&ah, g_ah);   cudaGetSymbolAddress((void**)&al, g_al);

    cudaFuncSetAttribute(attn_kernel,
                         cudaFuncAttributeMaxDynamicSharedMemorySize, ATTN_SMEM);
    cudaFuncSetAttribute(gemm_bf16x3_kernel,
                         cudaFuncAttributeMaxDynamicSharedMemorySize, GEMM_SMEM);

    // split-bf16 conversions
    {
        int n4 = BT * CC / 4;
        cvt_split_kernel<<<(n4 + 255)/256, 256>>>((const float4*)x,
            (__nv_bfloat162*)xh, (__nv_bfloat162*)xl, n4);
        n4 = C3 * CC / 4;
        cvt_split_kernel<<<(n4 + 255)/256, 256>>>((const float4*)Wqkv,
            (__nv_bfloat162*)wqh, (__nv_bfloat162*)wql, n4);
        n4 = CC * CC / 4;
        cvt_split_kernel<<<(n4 + 255)/256, 256>>>((const float4*)Wo,
            (__nv_bfloat162*)woh, (__nv_bfloat162*)wol, n4);
    }

    // 1) qkv = x @ Wqkv^T  (HMMA split-bf16)
    {
        dim3 grid(C3 / 128, BT / 128);
        gemm_bf16x3_kernel<<<grid, 256, GEMM_SMEM>>>(xh, xl, wqh, wql, qkv, BT, C3, CC);
    }
    // 2) causal flash attention (fp32)
    {
        dim3 grid(TT / 64, BB * HH);
        attn_kernel<<<grid, 256, ATTN_SMEM>>>();
    }
    // 3) out = att @ Wo^T  (HMMA split-bf16)
    {
        int n4 = BT * CC / 4;
        cvt_split_kernel<<<(n4 + 255)/256, 256>>>((const float4*)att,
            (__nv_bfloat162*)ah, (__nv_bfloat162*)al, n4);
        dim3 grid(CC / 128, BT / 128);
        gemm_bf16x3_kernel<<<grid, 256, GEMM_SMEM>>>(ah, al, woh, wol, out, BT, CC, CC);
    }
}

// round 4
// speedup vs baseline: 2.2014x; 1.5389x over previous
#include <cuda_runtime.h>
#include <cuda_bf16.h>
#include <cstdint>
#include <cstddef>

// Problem constants
#define BB 4
#define TT 2048
#define CC 1024
#define HH 16
#define DK 64
#define BT (BB*TT)        // 8192
#define C3 (3*CC)         // 3072

// ---------------------------------------------------------------------------
// Scratch (allocation-free rule: device globals)
// ---------------------------------------------------------------------------
__device__ float g_qkv[(size_t)BT * C3];   // 96 MB fp32 (q|k|v)
__device__ float g_att[(size_t)BT * CC];   // 32 MB fp32 attention out
__device__ __nv_bfloat16 g_xh[(size_t)BT * CC],  g_xl[(size_t)BT * CC];
__device__ __nv_bfloat16 g_wqh[(size_t)C3 * CC], g_wql[(size_t)C3 * CC];
__device__ __nv_bfloat16 g_woh[(size_t)CC * CC], g_wol[(size_t)CC * CC];
__device__ __nv_bfloat16 g_ah[(size_t)BT * CC],  g_al[(size_t)BT * CC];

extern __shared__ char dynsm[];

__device__ __forceinline__ uint32_t smem_to_u32(const void* p) {
    uint32_t a;
    asm("{ .reg .u64 t; cvta.to.shared.u64 t, %1; cvt.u32.u64 %0, t; }"
        : "=r"(a) : "l"(p));
    return a;
}

__device__ __forceinline__ void mma_bf16(float* c, const uint32_t* a, const uint32_t* b) {
    asm volatile("mma.sync.aligned.m16n8k16.row.col.f32.bf16.bf16.f32 "
        "{%0,%1,%2,%3}, {%4,%5,%6,%7}, {%8,%9}, {%0,%1,%2,%3};"
        : "+f"(c[0]), "+f"(c[1]), "+f"(c[2]), "+f"(c[3])
        : "r"(a[0]), "r"(a[1]), "r"(a[2]), "r"(a[3]), "r"(b[0]), "r"(b[1]));
}
__device__ __forceinline__ void ldsm_x4(uint32_t* r, uint32_t addr) {
    asm volatile("ldmatrix.sync.aligned.m8n8.x4.shared.b16 {%0,%1,%2,%3}, [%4];"
        : "=r"(r[0]), "=r"(r[1]), "=r"(r[2]), "=r"(r[3]) : "r"(addr));
}
__device__ __forceinline__ void ldsm_x2(uint32_t* r, uint32_t addr) {
    asm volatile("ldmatrix.sync.aligned.m8n8.x2.shared.b16 {%0,%1}, [%2];"
        : "=r"(r[0]), "=r"(r[1]) : "r"(addr));
}
#define CP_ASYNC16(dst, src) \
    asm volatile("cp.async.cg.shared.global [%0], [%1], 16;" :: "r"(dst), "l"(src))
#define CP_COMMIT()  asm volatile("cp.async.commit_group;" ::: "memory")
#define CP_WAIT1()   asm volatile("cp.async.wait_group 1;" ::: "memory")

// split helpers
__device__ __forceinline__ void split2(float a, float b, uint32_t& h, uint32_t& l) {
    __nv_bfloat16 ha = __float2bfloat16(a), hb = __float2bfloat16(b);
    __nv_bfloat16 la = __float2bfloat16(a - __bfloat162float(ha));
    __nv_bfloat16 lb = __float2bfloat16(b - __bfloat162float(hb));
    __nv_bfloat162 hp; hp.x = ha; hp.y = hb;
    __nv_bfloat162 lp; lp.x = la; lp.y = lb;
    h = *(uint32_t*)&hp; l = *(uint32_t*)&lp;
}

// ---------------------------------------------------------------------------
// Split-bf16 conversion kernel (for GEMM operands)
// ---------------------------------------------------------------------------
__global__ void cvt_split_kernel(const float4* __restrict__ src,
                                 __nv_bfloat162* __restrict__ hi,
                                 __nv_bfloat162* __restrict__ lo, int n4)
{
    int i = blockIdx.x * blockDim.x + threadIdx.x;
    if (i >= n4) return;
    float4 v = src[i];
    uint32_t h0, h1, l0, l1;
    split2(v.x, v.y, h0, l0);
    split2(v.z, v.w, h1, l1);
    hi[2*i] = *(__nv_bfloat162*)&h0; hi[2*i+1] = *(__nv_bfloat162*)&h1;
    lo[2*i] = *(__nv_bfloat162*)&l0; lo[2*i+1] = *(__nv_bfloat162*)&l1;
}

// ---------------------------------------------------------------------------
// HMMA split-bf16 GEMM (unchanged from R3): C = (Ah+Al)(Bh+Bl)^T, 3 products
// ---------------------------------------------------------------------------
#define RS_B    80
#define TILE_B  (128*RS_B)
#define STAGE_B (4*TILE_B)
#define STAGES  3
#define GEMM_SMEM (STAGES*STAGE_B)

__global__ __launch_bounds__(256, 1) void gemm_bf16x3_kernel(
    const __nv_bfloat16* __restrict__ Ah, const __nv_bfloat16* __restrict__ Al,
    const __nv_bfloat16* __restrict__ Bh, const __nv_bfloat16* __restrict__ Bl,
    float* __restrict__ C, int M, int N, int K)
{
    const int tid = threadIdx.x, lane = tid & 31, wid = tid >> 5;
    const int bm = blockIdx.y * 128, bn = blockIdx.x * 128;
    const int wr = wid >> 2, wc = wid & 3;
    const uint32_t sbase = smem_to_u32(dynsm);
    const int NC = K / 32;

    float acc[4][4][4];
#pragma unroll
    for (int i = 0; i < 4; i++)
#pragma unroll
        for (int j = 0; j < 4; j++)
#pragma unroll
            for (int v = 0; v < 4; v++) acc[i][j][v] = 0.0f;

    auto load_stage = [&](int st, int buf) {
        const int kk = st * 32;
        const uint32_t dstb = sbase + buf * STAGE_B;
#pragma unroll
        for (int i = 0; i < 8; i++) {
            int c = tid + i * 256;
            int tile = c >> 9;
            int rc = c & 511;
            int row = rc >> 2, kc = rc & 3;
            const __nv_bfloat16* src;
            if (tile == 0)      src = Ah + (size_t)(bm + row) * K + kk + kc * 8;
            else if (tile == 1) src = Al + (size_t)(bm + row) * K + kk + kc * 8;
            else if (tile == 2) src = Bh + (size_t)(bn + row) * K + kk + kc * 8;
            else                src = Bl + (size_t)(bn + row) * K + kk + kc * 8;
            uint32_t dst = dstb + tile * TILE_B + row * RS_B + kc * 16;
            CP_ASYNC16(dst, src);
        }
    };

    const uint32_t a_off0 = (wr * 64 + (lane & 15)) * RS_B + (lane >> 4) * 16;
    const uint32_t b_off0 = (wc * 32 + (lane & 7)) * RS_B + ((lane >> 3) & 1) * 16;

    load_stage(0, 0); CP_COMMIT();
    load_stage(1, 1); CP_COMMIT();

    for (int it = 0; it < NC; it++) {
        CP_WAIT1();
        __syncthreads();
        const int nxt = it + (STAGES - 1);
        if (nxt < NC) load_stage(nxt, nxt % STAGES);
        CP_COMMIT();

        const uint32_t tb = sbase + (it % STAGES) * STAGE_B;
#pragma unroll
        for (int ks = 0; ks < 2; ks++) {
            uint32_t ah[4][4], al[4][4];
#pragma unroll
            for (int mt = 0; mt < 4; mt++) {
                uint32_t aaddr = tb + a_off0 + mt * (16 * RS_B) + ks * 32;
                ldsm_x4(ah[mt], aaddr);
                ldsm_x4(al[mt], aaddr + TILE_B);
            }
#pragma unroll
            for (int nt = 0; nt < 4; nt++) {
                uint32_t baddr = tb + 2 * TILE_B + b_off0 + nt * (8 * RS_B) + ks * 32;
                uint32_t bh[2], bl[2];
                ldsm_x2(bh, baddr);
                ldsm_x2(bl, baddr + TILE_B);
#pragma unroll
                for (int mt = 0; mt < 4; mt++) mma_bf16(acc[mt][nt], ah[mt], bh);
#pragma unroll
                for (int mt = 0; mt < 4; mt++) mma_bf16(acc[mt][nt], al[mt], bh);
#pragma unroll
                for (int mt = 0; mt < 4; mt++) mma_bf16(acc[mt][nt], ah[mt], bl);
            }
        }
    }

    const int g = lane >> 2, t = lane & 3;
#pragma unroll
    for (int mt = 0; mt < 4; mt++) {
#pragma unroll
        for (int nt = 0; nt < 4; nt++) {
            int row = bm + wr * 64 + mt * 16 + g;
            int col = bn + wc * 32 + nt * 8 + t * 2;
            float2 v0 = make_float2(acc[mt][nt][0], acc[mt][nt][1]);
            float2 v1 = make_float2(acc[mt][nt][2], acc[mt][nt][3]);
            *(float2*)&C[(size_t)row * N + col]       = v0;
            *(float2*)&C[(size_t)(row + 8) * N + col] = v1;
        }
    }
}

// ---------------------------------------------------------------------------
// HMMA split-bf16 flash attention, causal.
// CTA = 128 queries x (b,h). 8 warps x 16 query rows. 64-key tiles.
// Q pre-scaled by 1/8, split hi/lo in register fragments.
// K split hi/lo in smem [key][d]; V split hi/lo transposed [d][key].
// S = QhKh+QlKh+QhKl ; PV = PhVh+PlVh+PhVl  (fp32 accumulators everywhere).
// Smem rows padded to 144B (mod 128 = 16 -> ldmatrix conflict-free).
// ---------------------------------------------------------------------------
#define RSA 144
#define ATT_SMEM (4 * 64 * RSA)   // 36864; Q stage uses same 36864 (2 x 128*144)

__global__ __launch_bounds__(256, 1) void attn_mma_kernel()
{
    const uint32_t sbase = smem_to_u32(dynsm);
    const int tid = threadIdx.x, lane = tid & 31, w = tid >> 5;
    const int qb = blockIdx.x;            // 128-query block
    const int b  = blockIdx.y >> 4;
    const int h  = blockIdx.y & 15;
    const size_t rbase = (size_t)b * TT;
    const int coff = h * DK;
    const int g = lane >> 2, t = lane & 3;

    // ---- stage Q (scaled by 1/8), split hi/lo into smem ----
    {
#pragma unroll
        for (int i = 0; i < 8; i++) {
            int idx = tid + i * 256;          // 0..2047
            int row = idx >> 4, c4 = idx & 15;
            const float* src = &g_qkv[(rbase + (size_t)qb * 128 + row) * C3 + coff + c4 * 4];
            float4 v = *(const float4*)src;
            v.x *= 0.125f; v.y *= 0.125f; v.z *= 0.125f; v.w *= 0.125f;
            uint32_t h0, h1, l0, l1;
            split2(v.x, v.y, h0, l0);
            split2(v.z, v.w, h1, l1);
            uint32_t off = row * RSA + c4 * 8;
            *(uint2*)(dynsm + off)         = make_uint2(h0, h1);
            *(uint2*)(dynsm + 18432 + off) = make_uint2(l0, l1);
        }
    }
    __syncthreads();

    // ---- per-warp Q fragments (kept in registers for whole kernel) ----
    uint32_t qh[4][4], ql[4][4];
#pragma unroll
    for (int kt = 0; kt < 4; kt++) {
        uint32_t addr = sbase + (w * 16 + (lane & 15)) * RSA + (lane >> 4) * 16 + kt * 32;
        ldsm_x4(qh[kt], addr);
        ldsm_x4(ql[kt], addr + 18432);
    }
    __syncthreads();

    // ---- online softmax state + O accumulators ----
    float oacc[8][4];
#pragma unroll
    for (int n = 0; n < 8; n++)
#pragma unroll
        for (int v = 0; v < 4; v++) oacc[n][v] = 0.0f;
    float m0 = -1e30f, m1 = -1e30f, l0s = 0.0f, l1s = 0.0f;

    const int qrow0 = qb * 128 + w * 16 + g;   // row for c0/c1; +8 for c2/c3
    const int jb_end = 2 * qb + 1;

    const uint32_t KhB = sbase, KlB = sbase + 9216;
    const uint32_t VhB = sbase + 18432, VlB = sbase + 27648;

    for (int jb = 0; jb <= jb_end; jb++) {
        // ---- load K (split, [key][d]) and V (split, transposed [d][key]) ----
#pragma unroll
        for (int i = 0; i < 4; i++) {
            int idx = tid + i * 256;          // 0..1023
            int row = idx >> 4, c4 = idx & 15;
            const float* base = &g_qkv[(rbase + (size_t)jb * 64 + row) * C3 + coff];
            float4 kv = *(const float4*)(base + CC + c4 * 4);
            uint32_t h0, h1, lo0, lo1;
            split2(kv.x, kv.y, h0, lo0);
            split2(kv.z, kv.w, h1, lo1);
            uint32_t off = row * RSA + c4 * 8;
            *(uint2*)(dynsm + off)        = make_uint2(h0, lo0 * 0 + h1);  // placeholder fix below
            // (written properly below)
            *(uint2*)(dynsm + off)        = make_uint2(h0, h1);
            *(uint2*)(dynsm + 9216 + off) = make_uint2(lo0, lo1);

            float4 vv = *(const float4*)(base + 2 * CC + c4 * 4);
            float vf[4] = {vv.x, vv.y, vv.z, vv.w};
#pragma unroll
            for (int j = 0; j < 4; j++) {
                int d = c4 * 4 + j;
                __nv_bfloat16 vh = __float2bfloat16(vf[j]);
                __nv_bfloat16 vl = __float2bfloat16(vf[j] - __bfloat162float(vh));
                *(__nv_bfloat16*)(dynsm + 18432 + d * RSA + row * 2) = vh;
                *(__nv_bfloat16*)(dynsm + 27648 + d * RSA + row * 2) = vl;
            }
        }
        __syncthreads();

        const bool active = (jb * 64 <= qb * 128 + w * 16 + 15);
        if (active) {
            // ---- S = Q K^T (3 products) ----
            float sacc[8][4];
#pragma unroll
            for (int n = 0; n < 8; n++)
#pragma unroll
                for (int v = 0; v < 4; v++) sacc[n][v] = 0.0f;
#pragma unroll
            for (int kt = 0; kt < 4; kt++) {
#pragma unroll
                for (int n = 0; n < 8; n++) {
                    uint32_t baddr = (n * 8 + (lane & 7)) * RSA + kt * 32 + ((lane >> 3) & 1) * 16;
                    uint32_t bh[2], bl[2];
                    ldsm_x2(bh, KhB + baddr);
                    ldsm_x2(bl, KlB + baddr);
                    mma_bf16(sacc[n], qh[kt], bh);
                    mma_bf16(sacc[n], ql[kt], bh);
                    mma_bf16(sacc[n], qh[kt], bl);
                }
            }

            // ---- causal mask ----
            const bool need_mask = (jb * 64 + 63 > qrow0);
            if (need_mask) {
#pragma unroll
                for (int n = 0; n < 8; n++) {
                    int colb = jb * 64 + n * 8 + t * 2;
                    if (colb     > qrow0) sacc[n][0] = -1e30f;
                    if (colb + 1 > qrow0) sacc[n][1] = -1e30f;
                    if (colb     > qrow0 + 8) sacc[n][2] = -1e30f;
                    if (colb + 1 > qrow0 + 8) sacc[n][3] = -1e30f;
                }
            }

            // ---- online softmax (rows g, g+8) ----
            float rmax0 = -1e30f, rmax1 = -1e30f;
#pragma unroll
            for (int n = 0; n < 8; n++) {
                rmax0 = fmaxf(rmax0, fmaxf(sacc[n][0], sacc[n][1]));
                rmax1 = fmaxf(rmax1, fmaxf(sacc[n][2], sacc[n][3]));
            }
            rmax0 = fmaxf(rmax0, __shfl_xor_sync(0xffffffffu, rmax0, 1));
            rmax0 = fmaxf(rmax0, __shfl_xor_sync(0xffffffffu, rmax0, 2));
            rmax1 = fmaxf(rmax1, __shfl_xor_sync(0xffffffffu, rmax1, 1));
            rmax1 = fmaxf(rmax1, __shfl_xor_sync(0xffffffffu, rmax1, 2));

            const float mn0 = fmaxf(m0, rmax0), mn1 = fmaxf(m1, rmax1);
            const float c0 = __expf(m0 - mn0), c1 = __expf(m1 - mn1);
            float rs0 = 0.0f, rs1 = 0.0f;
#pragma unroll
            for (int n = 0; n < 8; n++) {
                sacc[n][0] = __expf(sacc[n][0] - mn0);
                sacc[n][1] = __expf(sacc[n][1] - mn0);
                sacc[n][2] = __expf(sacc[n][2] - mn1);
                sacc[n][3] = __expf(sacc[n][3] - mn1);
                rs0 += sacc[n][0] + sacc[n][1];
                rs1 += sacc[n][2] + sacc[n][3];
            }
            rs0 += __shfl_xor_sync(0xffffffffu, rs0, 1);
            rs0 += __shfl_xor_sync(0xffffffffu, rs0, 2);
            rs1 += __shfl_xor_sync(0xffffffffu, rs1, 1);
            rs1 += __shfl_xor_sync(0xffffffffu, rs1, 2);
            l0s = l0s * c0 + rs0; l1s = l1s * c1 + rs1;
            m0 = mn0; m1 = mn1;
#pragma unroll
            for (int n = 0; n < 8; n++) {
                oacc[n][0] *= c0; oacc[n][1] *= c0;
                oacc[n][2] *= c1; oacc[n][3] *= c1;
            }

            // ---- O += P V (3 products); P frags from C-frag repack ----
#pragma unroll
            for (int kt = 0; kt < 4; kt++) {
                uint32_t pah[4], pal[4];
                split2(sacc[2*kt][0],   sacc[2*kt][1],   pah[0], pal[0]);
                split2(sacc[2*kt][2],   sacc[2*kt][3],   pah[1], pal[1]);
                split2(sacc[2*kt+1][0], sacc[2*kt+1][1], pah[2], pal[2]);
                split2(sacc[2*kt+1][2], sacc[2*kt+1][3], pah[3], pal[3]);
#pragma unroll
                for (int n = 0; n < 8; n++) {
                    uint32_t baddr = (n * 8 + (lane & 7)) * RSA + kt * 32 + ((lane >> 3) & 1) * 16;
                    uint32_t bvh[2], bvl[2];
                    ldsm_x2(bvh, VhB + baddr);
                    ldsm_x2(bvl, VlB + baddr);
                    mma_bf16(oacc[n], pah, bvh);
                    mma_bf16(oacc[n], pal, bvh);
                    mma_bf16(oacc[n], pah, bvl);
                }
            }
        }
        __syncthreads();
    }

    // ---- epilogue: normalize, store fp32 ----
    const float inv0 = 1.0f / l0s, inv1 = 1.0f / l1s;
    const size_t r0 = rbase + (size_t)qb * 128 + w * 16 + g;
#pragma unroll
    for (int n = 0; n < 8; n++) {
        int col = coff + n * 8 + t * 2;
        *(float2*)&g_att[r0 * CC + col]       = make_float2(oacc[n][0] * inv0, oacc[n][1] * inv0);
        *(float2*)&g_att[(r0 + 8) * CC + col] = make_float2(oacc[n][2] * inv1, oacc[n][3] * inv1);
    }
}

// ---------------------------------------------------------------------------
extern "C" void kernel_launch(void* const* d_in, const int* in_sizes, int n_in,
                              void* d_out, int out_size)
{
    const float* x    = (const float*)d_in[0];
    const float* Wqkv = (const float*)d_in[1];
    const float* Wo   = (const float*)d_in[2];
    float* out        = (float*)d_out;

    float *qkv, *att;
    __nv_bfloat16 *xh, *xl, *wqh, *wql, *woh, *wol, *ah, *al;
    cudaGetSymbolAddress((void**)&qkv, g_qkv);
    cudaGetSymbolAddress((void**)&att, g_att);
    cudaGetSymbolAddress((void**)&xh, g_xh);   cudaGetSymbolAddress((void**)&xl, g_xl);
    cudaGetSymbolAddress((void**)&wqh, g_wqh); cudaGetSymbolAddress((void**)&wql, g_wql);
    cudaGetSymbolAddress((void**)&woh, g_woh); cudaGetSymbolAddress((void**)&wol, g_wol);
    cudaGetSymbolAddress((void**)&ah, g_ah);   cudaGetSymbolAddress((void**)&al, g_al);

    cudaFuncSetAttribute(gemm_bf16x3_kernel,
                         cudaFuncAttributeMaxDynamicSharedMemorySize, GEMM_SMEM);

    // split-bf16 conversions for GEMM operands
    {
        int n4 = BT * CC / 4;
        cvt_split_kernel<<<(n4 + 255)/256, 256>>>((const float4*)x,
            (__nv_bfloat162*)xh, (__nv_bfloat162*)xl, n4);
        n4 = C3 * CC / 4;
        cvt_split_kernel<<<(n4 + 255)/256, 256>>>((const float4*)Wqkv,
            (__nv_bfloat162*)wqh, (__nv_bfloat162*)wql, n4);
        n4 = CC * CC / 4;
        cvt_split_kernel<<<(n4 + 255)/256, 256>>>((const float4*)Wo,
            (__nv_bfloat162*)woh, (__nv_bfloat162*)wol, n4);
    }

    // 1) qkv = x @ Wqkv^T
    {
        dim3 grid(C3 / 128, BT / 128);
        gemm_bf16x3_kernel<<<grid, 256, GEMM_SMEM>>>(xh, xl, wqh, wql, qkv, BT, C3, CC);
    }
    // 2) causal flash attention (HMMA split-bf16)
    {
        dim3 grid(TT / 128, BB * HH);
        attn_mma_kernel<<<grid, 256, ATT_SMEM>>>();
    }
    // 3) out = att @ Wo^T
    {
        int n4 = BT * CC / 4;
        cvt_split_kernel<<<(n4 + 255)/256, 256>>>((const float4*)att,
            (__nv_bfloat162*)ah, (__nv_bfloat162*)al, n4);
        dim3 grid(CC / 128, BT / 128);
        gemm_bf16x3_kernel<<<grid, 256, GEMM_SMEM>>>(ah, al, woh, wol, out, BT, CC, CC);
    }
}